// round 16
// baseline (speedup 1.0000x reference)
#include <cuda_runtime.h>
#include <cuda_bf16.h>
#include <stdint.h>
#include <math.h>

#define NHYP 4096
#define NPREM 4096
#define HEADS 4
#define ATN 128
#define DCTX 512
#define BERT 768
#define VD 192   // BERT/HEADS
#define QK_STRIDE 136   // bf16 elems per smem row (128 + 8 pad)
// scale * log2(e) folded into Q so score MMA yields log2-domain values
#define SC_LOG2E 0.127517425f

// ---------------- scratch (device globals; no allocations allowed) ----------------
__device__ __nv_bfloat16 g_Qhb[(size_t)HEADS * NHYP * ATN];    // [h][n][d]  (pre-scaled)
__device__ __nv_bfloat16 g_Khb[(size_t)HEADS * NPREM * ATN];   // [h][m][d]
__device__ __nv_bfloat16 g_Vt[(size_t)BERT * NPREM];           // [col][m] (col = h*192+e)
__device__ float g_att[(size_t)NHYP * BERT];
__device__ float g_h1[(size_t)NHYP * 256];
__device__ float g_h2[(size_t)NHYP * 128];
__device__ int   g_bp[NPREM];
__device__ int   g_bh[NHYP];
__device__ int   g_mlo[NHYP];
__device__ int   g_mhi[NHYP];
__device__ __nv_bfloat16 g_Wq_t[DCTX * DCTX];
__device__ __nv_bfloat16 g_Wk_t[DCTX * DCTX];
__device__ __nv_bfloat16 g_Wv_t[BERT * BERT];
__device__ __nv_bfloat16 g_W1_t[256 * (DCTX + BERT)];

// ================= warp-MMA / async helpers =================
__device__ __forceinline__ uint32_t smem_u32(const void* p) {
    uint32_t a;
    asm("{ .reg .u64 t; cvta.to.shared.u64 t, %1; cvt.u32.u64 %0, t; }" : "=r"(a) : "l"(p));
    return a;
}
__device__ __forceinline__ void ldm_x4(uint32_t* r, uint32_t addr) {
    asm volatile("ldmatrix.sync.aligned.m8n8.x4.shared.b16 {%0,%1,%2,%3}, [%4];"
        : "=r"(r[0]), "=r"(r[1]), "=r"(r[2]), "=r"(r[3]) : "r"(addr));
}
__device__ __forceinline__ void mma_bf16(float* c, const uint32_t* a, uint32_t b0, uint32_t b1) {
    asm volatile("mma.sync.aligned.m16n8k16.row.col.f32.bf16.bf16.f32 "
        "{%0,%1,%2,%3}, {%4,%5,%6,%7}, {%8,%9}, {%0,%1,%2,%3};"
        : "+f"(c[0]), "+f"(c[1]), "+f"(c[2]), "+f"(c[3])
        : "r"(a[0]), "r"(a[1]), "r"(a[2]), "r"(a[3]), "r"(b0), "r"(b1));
}
__device__ __forceinline__ void cp16(uint32_t dst, const void* src) {
    asm volatile("cp.async.cg.shared.global [%0], [%1], 16;" :: "r"(dst), "l"(src));
}
__device__ __forceinline__ float ex2f(float x) {
    float y;
    asm("ex2.approx.f32 %0, %1;" : "=f"(y) : "f"(x));
    return y;
}
__device__ __forceinline__ uint4 pack_bf16x8(float4 f0, float4 f1) {
    __nv_bfloat162 p0 = __floats2bfloat162_rn(f0.x, f0.y);
    __nv_bfloat162 p1 = __floats2bfloat162_rn(f0.z, f0.w);
    __nv_bfloat162 p2 = __floats2bfloat162_rn(f1.x, f1.y);
    __nv_bfloat162 p3 = __floats2bfloat162_rn(f1.z, f1.w);
    uint4 u;
    u.x = *(uint32_t*)&p0; u.y = *(uint32_t*)&p1;
    u.z = *(uint32_t*)&p2; u.w = *(uint32_t*)&p3;
    return u;
}

// ---------------- prep kernels ----------------
__device__ __forceinline__ void prep_batch_one(const int* __restrict__ raw, int* __restrict__ dst, int n)
{
    __shared__ int flag;
    int t = threadIdx.x;
    if (t == 0) flag = 0;
    __syncthreads();
    int acc = 0;
    for (int i = 2 * t + 1; i < n; i += 512) acc |= raw[i];
    if (acc) atomicOr(&flag, 1);
    __syncthreads();
    bool is32 = (flag != 0);
    for (int i = t; i < n; i += 256)
        dst[i] = is32 ? raw[i] : raw[2 * i];
}

__global__ void prep_batch2_kernel(const int* __restrict__ rawp, const int* __restrict__ rawh)
{
    if (blockIdx.x == 0) prep_batch_one(rawp, g_bp, NPREM);
    else                 prep_batch_one(rawh, g_bh, NHYP);
}

// masked premise columns for hyp row n form contiguous range [mlo, mhi) (batch_p sorted)
__global__ void prep_ranges_kernel()
{
    int n = blockIdx.x * 256 + threadIdx.x;
    int b = g_bh[n];
    int lo = 0, hi = NPREM;
    while (lo < hi) { int mid = (lo + hi) >> 1; if (g_bp[mid] < b) lo = mid + 1; else hi = mid; }
    int s = lo;
    lo = 0; hi = NPREM;
    while (lo < hi) { int mid = (lo + hi) >> 1; if (g_bp[mid] < b + 1) lo = mid + 1; else hi = mid; }
    g_mlo[n] = s;
    g_mhi[n] = lo;
}

// all 4 weight transposes (fp32 [R][C] -> bf16 [C][R]) in one launch; 1408 tiles
__global__ void transpose_all_kernel(const float* __restrict__ Wq, const float* __restrict__ Wk,
                                     const float* __restrict__ Wv, const float* __restrict__ W1)
{
    __shared__ float tile[32][33];
    int t = blockIdx.x;
    const float* W;
    __nv_bfloat16* Wt;
    int R, C;
    if (t < 256)       { W = Wq; Wt = g_Wq_t; R = DCTX; C = DCTX; }
    else if (t < 512)  { t -= 256;  W = Wk; Wt = g_Wk_t; R = DCTX; C = DCTX; }
    else if (t < 1088) { t -= 512;  W = Wv; Wt = g_Wv_t; R = BERT; C = BERT; }
    else               { t -= 1088; W = W1; Wt = g_W1_t; R = DCTX + BERT; C = 256; }
    int tilesX = C >> 5;
    int c0 = (t % tilesX) * 32, r0 = (t / tilesX) * 32;
    int tx = threadIdx.x, ty = threadIdx.y;   // 32 x 8
#pragma unroll
    for (int j = 0; j < 4; j++)
        tile[ty + j * 8][tx] = W[(size_t)(r0 + ty + j * 8) * C + (c0 + tx)];
    __syncthreads();
#pragma unroll
    for (int j = 0; j < 4; j++)
        Wt[(size_t)(c0 + ty + j * 8) * R + (r0 + tx)] = __float2bfloat16(tile[tx][ty + j * 8]);
}

// ---------------- merged bf16 warp-MMA projections (V first for LPT scheduling) ----------------
// block decode: [0,192) V (long jobs), [192,320) Q, [320,448) K
__global__ __launch_bounds__(256, 2) void proj_all(const float* __restrict__ ctx_h,
                                                   const float* __restrict__ ctx_p,
                                                   const float* __restrict__ lhs_p,
                                                   const float* __restrict__ bq,
                                                   const float* __restrict__ bk,
                                                   const float* __restrict__ bv)
{
    extern __shared__ __nv_bfloat16 smem[];
    __nv_bfloat16* As = smem;
    int tid = threadIdx.x, wid = tid >> 5, lane = tid & 31;

    int t = blockIdx.x;
    int mode, K, c0, n0;
    const float* A;
    const __nv_bfloat16* Wt;
    const float* bias;
    if (t < 192)      { mode = 2; K = BERT; A = lhs_p; Wt = g_Wv_t; bias = bv; c0 = (t % 6) * 128; n0 = (t / 6) * 128; }
    else if (t < 320) { t -= 192; mode = 0; K = DCTX; A = ctx_h; Wt = g_Wq_t; bias = bq; c0 = (t & 3) * 128; n0 = (t >> 2) * 128; }
    else              { t -= 320; mode = 1; K = DCTX; A = ctx_p; Wt = g_Wk_t; bias = bk; c0 = (t & 3) * 128; n0 = (t >> 2) * 128; }

    uint32_t bsu = smem_u32(smem) + 128 * QK_STRIDE * 2;

    int wr = wid >> 1, wc = wid & 1;
    uint32_t abase = smem_u32(As) + (uint32_t)(wr * 32 + (lane & 15)) * (QK_STRIDE * 2) + (lane >> 4) * 16;
    uint32_t bbase = bsu + (uint32_t)(wc * 64 + (lane & 7) + ((lane & 16) >> 1)) * (QK_STRIDE * 2)
                     + ((lane >> 3) & 1) * 16;

    float c[2][8][4] = {};
    for (int kt = 0; kt < K / 128; kt++) {
        int k0 = kt * 128;
        for (int i = tid; i < 2048; i += 256) {
            int r = i >> 4, cc = (i & 15) * 8;
            cp16(bsu + (uint32_t)(r * QK_STRIDE + cc) * 2, &Wt[(size_t)(c0 + r) * K + k0 + cc]);
        }
        asm volatile("cp.async.commit_group;" ::: "memory");
        for (int i = tid; i < 2048; i += 256) {
            int r = i >> 4, cc = (i & 15) * 8;
            const float* ap = &A[(size_t)(n0 + r) * K + k0 + cc];
            *(uint4*)&As[r * QK_STRIDE + cc] = pack_bf16x8(*(const float4*)ap, *(const float4*)(ap + 4));
        }
        asm volatile("cp.async.wait_group 0;" ::: "memory");
        __syncthreads();
#pragma unroll
        for (int s = 0; s < 8; s++) {
            uint32_t a[2][4], b[4][4];
#pragma unroll
            for (int mi = 0; mi < 2; mi++) ldm_x4(a[mi], abase + mi * 16 * QK_STRIDE * 2 + s * 32);
#pragma unroll
            for (int ni = 0; ni < 4; ni++) ldm_x4(b[ni], bbase + ni * 16 * QK_STRIDE * 2 + s * 32);
#pragma unroll
            for (int mi = 0; mi < 2; mi++)
#pragma unroll
                for (int nb = 0; nb < 8; nb++)
                    mma_bf16(c[mi][nb], a[mi], b[nb >> 1][(nb & 1) * 2], b[nb >> 1][(nb & 1) * 2 + 1]);
        }
        __syncthreads();
    }

    int g = lane >> 2, tq = lane & 3;
#pragma unroll
    for (int mi = 0; mi < 2; mi++) {
        int row = n0 + wr * 32 + mi * 16 + g;
#pragma unroll
        for (int nb = 0; nb < 8; nb++) {
            int col = c0 + wc * 64 + nb * 8 + tq * 2;
            float b0 = bias[col], b1 = bias[col + 1];
            float v0 = c[mi][nb][0] + b0, v1 = c[mi][nb][1] + b1;
            float v2 = c[mi][nb][2] + b0, v3 = c[mi][nb][3] + b1;
            if (mode == 0) {
                v0 *= SC_LOG2E; v1 *= SC_LOG2E; v2 *= SC_LOG2E; v3 *= SC_LOG2E;
                g_Qhb[((size_t)(col & 3) * NHYP + row) * ATN + (col >> 2)]             = __float2bfloat16(v0);
                g_Qhb[((size_t)((col + 1) & 3) * NHYP + row) * ATN + ((col + 1) >> 2)] = __float2bfloat16(v1);
                g_Qhb[((size_t)(col & 3) * NHYP + row + 8) * ATN + (col >> 2)]             = __float2bfloat16(v2);
                g_Qhb[((size_t)((col + 1) & 3) * NHYP + row + 8) * ATN + ((col + 1) >> 2)] = __float2bfloat16(v3);
            } else if (mode == 1) {
                g_Khb[((size_t)(col & 3) * NPREM + row) * ATN + (col >> 2)]             = __float2bfloat16(v0);
                g_Khb[((size_t)((col + 1) & 3) * NPREM + row) * ATN + ((col + 1) >> 2)] = __float2bfloat16(v1);
                g_Khb[((size_t)(col & 3) * NPREM + row + 8) * ATN + (col >> 2)]             = __float2bfloat16(v2);
                g_Khb[((size_t)((col + 1) & 3) * NPREM + row + 8) * ATN + ((col + 1) >> 2)] = __float2bfloat16(v3);
            } else {
                g_Vt[(size_t)col * NPREM + row]           = __float2bfloat16(v0);
                g_Vt[(size_t)(col + 1) * NPREM + row]     = __float2bfloat16(v1);
                g_Vt[(size_t)col * NPREM + row + 8]       = __float2bfloat16(v2);
                g_Vt[(size_t)(col + 1) * NPREM + row + 8] = __float2bfloat16(v3);
            }
        }
    }
}

// ---------------- bf16 warp-MMA MLP1 (64-row tile -> 128 CTAs, 2 CTAs/SM) ----------------
__global__ __launch_bounds__(256, 2) void mlp1_bf(const float* __restrict__ ctx_h,
                                                  const float* __restrict__ lhs_h,
                                                  const __nv_bfloat16* __restrict__ Wt,
                                                  const float* __restrict__ bias)
{
    const int K = DCTX + BERT;
    extern __shared__ __nv_bfloat16 smem[];
    __nv_bfloat16* As = smem;
    uint32_t bsu = smem_u32(smem) + 64 * QK_STRIDE * 2;
    int tid = threadIdx.x, wid = tid >> 5, lane = tid & 31;
    int c0 = blockIdx.x * 128, n0 = blockIdx.y * 64;

    int wr = wid >> 1, wc = wid & 1;
    uint32_t abase = smem_u32(As) + (uint32_t)(wr * 16 + (lane & 15)) * (QK_STRIDE * 2) + (lane >> 4) * 16;
    uint32_t bbase = bsu + (uint32_t)(wc * 64 + (lane & 7) + ((lane & 16) >> 1)) * (QK_STRIDE * 2)
                     + ((lane >> 3) & 1) * 16;

    float c[8][4] = {};
    for (int kt = 0; kt < K / 128; kt++) {
        int k0 = kt * 128;
        for (int i = tid; i < 2048; i += 256) {
            int r = i >> 4, cc = (i & 15) * 8;
            cp16(bsu + (uint32_t)(r * QK_STRIDE + cc) * 2, &Wt[(size_t)(c0 + r) * K + k0 + cc]);
        }
        asm volatile("cp.async.commit_group;" ::: "memory");
        for (int i = tid; i < 1024; i += 256) {
            int r = i >> 4, cc = (i & 15) * 8;
            int kg = k0 + cc;
            int row = n0 + r;
            float4 f0, f1;
            if (kg < DCTX) {
                const float* ap = &ctx_h[(size_t)row * DCTX + kg];
                f0 = *(const float4*)ap; f1 = *(const float4*)(ap + 4);
            } else {
                int idx = kg - DCTX;
                const float* lp = &lhs_h[(size_t)row * BERT + idx];
                const float* tp = &g_att[(size_t)row * BERT + idx];
                float4 l0 = *(const float4*)lp, l1 = *(const float4*)(lp + 4);
                float4 a0 = *(const float4*)tp, a1 = *(const float4*)(tp + 4);
                f0 = make_float4(l0.x - a0.x, l0.y - a0.y, l0.z - a0.z, l0.w - a0.w);
                f1 = make_float4(l1.x - a1.x, l1.y - a1.y, l1.z - a1.z, l1.w - a1.w);
            }
            *(uint4*)&As[r * QK_STRIDE + cc] = pack_bf16x8(f0, f1);
        }
        asm volatile("cp.async.wait_group 0;" ::: "memory");
        __syncthreads();
#pragma unroll
        for (int s = 0; s < 8; s++) {
            uint32_t a[4], b[4][4];
            ldm_x4(a, abase + s * 32);
#pragma unroll
            for (int ni = 0; ni < 4; ni++) ldm_x4(b[ni], bbase + ni * 16 * QK_STRIDE * 2 + s * 32);
#pragma unroll
            for (int nb = 0; nb < 8; nb++)
                mma_bf16(c[nb], a, b[nb >> 1][(nb & 1) * 2], b[nb >> 1][(nb & 1) * 2 + 1]);
        }
        __syncthreads();
    }

    int g = lane >> 2, tq = lane & 3;
    int row = n0 + wr * 16 + g;
#pragma unroll
    for (int nb = 0; nb < 8; nb++) {
        int col = c0 + wc * 64 + nb * 8 + tq * 2;
        float vv[4] = { c[nb][0] + bias[col], c[nb][1] + bias[col + 1],
                        c[nb][2] + bias[col], c[nb][3] + bias[col + 1] };
#pragma unroll
        for (int q = 0; q < 4; q++)
            vv[q] = 0.5f * vv[q] * (1.0f + erff(vv[q] * 0.70710678118654752f));
        g_h1[(size_t)row * 256 + col]           = vv[0];
        g_h1[(size_t)row * 256 + col + 1]       = vv[1];
        g_h1[(size_t)(row + 8) * 256 + col]     = vv[2];
        g_h1[(size_t)(row + 8) * 256 + col + 1] = vv[3];
    }
}

// ---------------- fused flash attention: 512 threads, e-split warp groups ----------------
// 16 warps: warp w = (eg, wrow); eg = w>>3 owns e[eg*96, eg*96+96); wrow = w&7 owns rows [wrow*16,+16).
// Score/softmax duplicated across eg (identical values); PV + epilogue split by eg.
#define FL_KOFF   (128 * QK_STRIDE)
#define FL_VOFF   (384 * QK_STRIDE)
#define FL_SMEM   (768 * QK_STRIDE * 2)
#define FL_NT     (NPREM / 128)
__global__ __launch_bounds__(512) void attn_flash()
{
    extern __shared__ __nv_bfloat16 smem[];
    __nv_bfloat16* Qs = smem;
    int tid = threadIdx.x, wid = tid >> 5, lane = tid & 31;
    int eg = wid >> 3, wrow = wid & 7;
    int n0 = blockIdx.x * 128, h = blockIdx.y;
    int e0g = h * VD;
    const __nv_bfloat16* Q  = g_Qhb + (size_t)h * NHYP * ATN;
    const __nv_bfloat16* Kp = g_Khb + (size_t)h * NPREM * ATN;

    uint32_t ksu = smem_u32(smem) + FL_KOFF * 2;
    uint32_t vsu = smem_u32(smem) + FL_VOFF * 2;

    for (int i = tid; i < 2048; i += 512) {
        int r = i >> 4, c = (i & 15) * 8;
        *(uint4*)&Qs[r * QK_STRIDE + c] = *(const uint4*)&Q[(size_t)(n0 + r) * ATN + c];
    }

    auto issue = [&](int tt) {
        int b = tt & 1;
        int m0 = tt * 128;
        uint32_t kd = ksu + (uint32_t)b * (128 * QK_STRIDE * 2);
        uint32_t vd = vsu + (uint32_t)b * (192 * QK_STRIDE * 2);
        for (int i = tid; i < 2048; i += 512) {
            int r = i >> 4, c = (i & 15) * 8;
            cp16(kd + (uint32_t)(r * QK_STRIDE + c) * 2, Kp + (size_t)(m0 + r) * ATN + c);
        }
        for (int i = tid; i < 3072; i += 512) {
            int r = i >> 4, c = (i & 15) * 8;
            cp16(vd + (uint32_t)(r * QK_STRIDE + c) * 2, g_Vt + (size_t)(e0g + r) * NPREM + m0 + c);
        }
        asm volatile("cp.async.commit_group;" ::: "memory");
    };

    issue(0);

    int g = lane >> 2, tq = lane & 3;
    int r0g = n0 + wrow * 16 + g;
    unsigned mlo0 = (unsigned)g_mlo[r0g];
    unsigned mw0  = (unsigned)(g_mhi[r0g] - g_mlo[r0g]);
    unsigned mlo1 = (unsigned)g_mlo[r0g + 8];
    unsigned mw1  = (unsigned)(g_mhi[r0g + 8] - g_mlo[r0g + 8]);

    uint32_t qbase = smem_u32(Qs) + (uint32_t)(wrow * 16 + (lane & 15)) * (QK_STRIDE * 2) + (lane >> 4) * 16;
    uint32_t kvlane = (uint32_t)((lane & 7) + ((lane & 16) >> 1)) * (QK_STRIDE * 2) + ((lane >> 3) & 1) * 16;
    uint32_t voff = (uint32_t)(eg * 96) * (QK_STRIDE * 2);

    float l0 = 0.f, l1 = 0.f;
    float pacc[12][4] = {};

    for (int t = 0; t < FL_NT; t++) {
        int b = t & 1;
        if (t + 1 < FL_NT) {
            issue(t + 1);
            asm volatile("cp.async.wait_group 1;" ::: "memory");
        } else {
            asm volatile("cp.async.wait_group 0;" ::: "memory");
        }
        __syncthreads();

        uint32_t kb0 = ksu + (uint32_t)b * (128 * QK_STRIDE * 2) + kvlane;
        uint32_t vbase = vsu + (uint32_t)b * (192 * QK_STRIDE * 2) + kvlane + voff;
        int m0 = t * 128;

#pragma unroll
        for (int half = 0; half < 2; half++) {
            uint32_t kb = kb0 + (uint32_t)half * 64 * (QK_STRIDE * 2);

            // --- score for 64 m-cols (log2 domain); duplicated across eg groups ---
            float sacc[8][4] = {};
#pragma unroll
            for (int ks = 0; ks < 8; ks++) {
                uint32_t a[4];
                ldm_x4(a, qbase + ks * 32);
#pragma unroll
                for (int nj = 0; nj < 4; nj++) {
                    uint32_t bb[4];
                    ldm_x4(bb, kb + nj * 16 * (QK_STRIDE * 2) + ks * 32);
                    mma_bf16(sacc[2 * nj],     a, bb[0], bb[1]);
                    mma_bf16(sacc[2 * nj + 1], a, bb[2], bb[3]);
                }
            }

            // --- exp2 + range mask zero + accumulate l + pack P fragments ---
            uint32_t pfrag[4][4];
#pragma unroll
            for (int j = 0; j < 8; j++) {
                unsigned ci = (unsigned)(m0 + half * 64 + j * 8 + tq * 2);
                float v0 = ex2f(sacc[j][0]);
                float v1 = ex2f(sacc[j][1]);
                float v2 = ex2f(sacc[j][2]);
                float v3 = ex2f(sacc[j][3]);
                if (ci - mlo0 < mw0)     v0 = 0.f;
                if (ci + 1 - mlo0 < mw0) v1 = 0.f;
                if (ci - mlo1 < mw1)     v2 = 0.f;
                if (ci + 1 - mlo1 < mw1) v3 = 0.f;
                l0 += v0 + v1;
                l1 += v2 + v3;
                __nv_bfloat162 p01 = __floats2bfloat162_rn(v0, v1);
                __nv_bfloat162 p23 = __floats2bfloat162_rn(v2, v3);
                pfrag[j >> 1][(j & 1) * 2]     = *(uint32_t*)&p01;
                pfrag[j >> 1][(j & 1) * 2 + 1] = *(uint32_t*)&p23;
            }

            // --- PV over this half's 64 k, this group's 96 e-cols ---
#pragma unroll
            for (int ks = 0; ks < 4; ks++) {
                int ksg = half * 4 + ks;
#pragma unroll
                for (int ej = 0; ej < 6; ej++) {
                    uint32_t bb[4];
                    ldm_x4(bb, vbase + ej * 16 * (QK_STRIDE * 2) + ksg * 32);
                    mma_bf16(pacc[2 * ej],     pfrag[ks], bb[0], bb[1]);
                    mma_bf16(pacc[2 * ej + 1], pfrag[ks], bb[2], bb[3]);
                }
            }
        }
        __syncthreads();
    }

    // reduce l across the 4 tq lanes (once, after the loop)
    l0 += __shfl_xor_sync(0xffffffffu, l0, 1);
    l0 += __shfl_xor_sync(0xffffffffu, l0, 2);
    l1 += __shfl_xor_sync(0xffffffffu, l1, 1);
    l1 += __shfl_xor_sync(0xffffffffu, l1, 2);

    float inv0 = 1.0f / l0, inv1 = 1.0f / l1;
#pragma unroll
    for (int ej = 0; ej < 12; ej++) {
        int e = e0g + eg * 96 + ej * 8 + tq * 2;
        *(float2*)&g_att[(size_t)r0g * BERT + e]       = make_float2(pacc[ej][0] * inv0, pacc[ej][1] * inv0);
        *(float2*)&g_att[(size_t)(r0g + 8) * BERT + e] = make_float2(pacc[ej][2] * inv1, pacc[ej][3] * inv1);
    }
}

// ---------------- h2 = LayerNorm(h1 @ W2), 32-row tiles (grid 128) ----------------
__global__ void mlp2_kernel(const float* __restrict__ W2, const float* __restrict__ lng,
                            const float* __restrict__ lnb)
{
    __shared__ float smbuf[32 * 36 + 32 * 132 + 64];
    float* Fts = smbuf;
    float* Ws2 = smbuf + 32 * 36;
    int tid = threadIdx.x;
    int n0 = blockIdx.x * 32;
    int tx = tid & 15, ty = tid >> 4;
    float acc[2][8] = {};
    for (int k0 = 0; k0 < 256; k0 += 32) {
#pragma unroll
        for (int it = 0; it < 4; it++) {
            int e = tid + it * 256;
            int r = e >> 5, kk = e & 31;
            Fts[kk * 36 + r] = g_h1[(size_t)(n0 + r) * 256 + (k0 + kk)];
        }
#pragma unroll
        for (int it = 0; it < 16; it++) {
            int e = tid + it * 256;
            int kk = e >> 7, c = e & 127;
            Ws2[kk * 132 + c] = W2[(size_t)(k0 + kk) * 128 + c];
        }
        __syncthreads();
#pragma unroll
        for (int kk = 0; kk < 32; kk++) {
            float2 a  = *(const float2*)&Fts[kk * 36 + ty * 2];
            float4 b0 = *(const float4*)&Ws2[kk * 132 + tx * 4];
            float4 b1v = *(const float4*)&Ws2[kk * 132 + 64 + tx * 4];
            float av[2] = {a.x, a.y};
            float bv[8] = {b0.x, b0.y, b0.z, b0.w, b1v.x, b1v.y, b1v.z, b1v.w};
#pragma unroll
            for (int i = 0; i < 2; i++)
#pragma unroll
                for (int j = 0; j < 8; j++)
                    acc[i][j] += av[i] * bv[j];
        }
        __syncthreads();
    }
    float* H2s = smbuf;
    float* mu  = smbuf + 32 * 132;
    float* rs  = mu + 32;
#pragma unroll
    for (int i = 0; i < 2; i++) {
        int r = ty * 2 + i;
#pragma unroll
        for (int j = 0; j < 8; j++) {
            int c = (j < 4) ? (tx * 4 + j) : (64 + tx * 4 + (j - 4));
            H2s[r * 132 + c] = acc[i][j];
        }
    }
    __syncthreads();
    if (tid < 32) {
        float s = 0.f;
        for (int c = 0; c < 128; c++) s += H2s[tid * 132 + c];
        float m = s * (1.0f / 128.0f);
        float vv = 0.f;
        for (int c = 0; c < 128; c++) { float d = H2s[tid * 132 + c] - m; vv += d * d; }
        mu[tid] = m;
        rs[tid] = rsqrtf(vv * (1.0f / 128.0f) + 1e-5f);
    }
    __syncthreads();
#pragma unroll
    for (int it = 0; it < 16; it++) {
        int e = tid + it * 256;
        int r = e >> 7, c = e & 127;
        float v = (H2s[r * 132 + c] - mu[r]) * rs[r] * lng[c] + lnb[c];
        g_h2[(size_t)(n0 + r) * 128 + c] = v;
    }
}

// ---------------- segment-mean pool + classifier ----------------
__global__ void final_kernel(const float* __restrict__ Wc,
                             const float* __restrict__ bc, float* __restrict__ out)
{
    int b = blockIdx.x;
    int c = threadIdx.x;
    int lo = 0, hi = NHYP;
    while (lo < hi) { int mid = (lo + hi) >> 1; if (g_bh[mid] < b) lo = mid + 1; else hi = mid; }
    int start = lo;
    lo = 0; hi = NHYP;
    while (lo < hi) { int mid = (lo + hi) >> 1; if (g_bh[mid] < b + 1) lo = mid + 1; else hi = mid; }
    int end = lo;
    float s = 0.f;
    for (int r = start; r < end; r++) s += g_h2[(size_t)r * 128 + c];
    int cnt = end - start;
    float pooled = s / (float)(cnt > 1 ? cnt : 1);
    __shared__ float ps[128];
    ps[c] = pooled;
    __syncthreads();
    if (c < 3) {
        float o = bc[c];
        for (int j = 0; j < 128; j++) o += ps[j] * Wc[j * 3 + c];
        out[b * 3 + c] = o;
    }
}

// ---------------- launcher ----------------
#define PROJ_SMEM  (2 * 128 * QK_STRIDE * 2)
#define MLP1_SMEM  ((64 + 128) * QK_STRIDE * 2)

extern "C" void kernel_launch(void* const* d_in, const int* in_sizes, int n_in,
                              void* d_out, int out_size)
{
    const float* ctx_p = (const float*)d_in[0];
    const float* ctx_h = (const float*)d_in[1];
    const float* lhs_p = (const float*)d_in[2];
    const float* lhs_h = (const float*)d_in[3];
    const int* batch_p_raw = (const int*)d_in[4];
    const int* batch_h_raw = (const int*)d_in[5];
    const float* Wq = (const float*)d_in[6];
    const float* bq = (const float*)d_in[7];
    const float* Wk = (const float*)d_in[8];
    const float* bk = (const float*)d_in[9];
    const float* Wv = (const float*)d_in[10];
    const float* bv = (const float*)d_in[11];
    const float* W1 = (const float*)d_in[12];
    const float* b1 = (const float*)d_in[13];
    const float* W2 = (const float*)d_in[14];
    const float* lng = (const float*)d_in[15];
    const float* lnb = (const float*)d_in[16];
    const float* Wc = (const float*)d_in[17];
    const float* bc = (const float*)d_in[18];
    float* out = (float*)d_out;

    __nv_bfloat16* w1_t; cudaGetSymbolAddress((void**)&w1_t, g_W1_t);

    cudaFuncSetAttribute(proj_all,   cudaFuncAttributeMaxDynamicSharedMemorySize, PROJ_SMEM);
    cudaFuncSetAttribute(mlp1_bf,    cudaFuncAttributeMaxDynamicSharedMemorySize, MLP1_SMEM);
    cudaFuncSetAttribute(attn_flash, cudaFuncAttributeMaxDynamicSharedMemorySize, FL_SMEM);

    prep_batch2_kernel<<<2, 256>>>(batch_p_raw, batch_h_raw);
    prep_ranges_kernel<<<NHYP / 256, 256>>>();

    transpose_all_kernel<<<1408, dim3(32, 8)>>>(Wq, Wk, Wv, W1);

    proj_all<<<448, 256, PROJ_SMEM>>>(ctx_h, ctx_p, lhs_p, bq, bk, bv);

    attn_flash<<<dim3(NHYP / 128, HEADS), 512, FL_SMEM>>>();

    mlp1_bf<<<dim3(2, NHYP / 64), 256, MLP1_SMEM>>>(ctx_h, lhs_h, w1_t, b1);
    mlp2_kernel<<<NHYP / 32, 256>>>(W2, lng, lnb);
    final_kernel<<<32, 128>>>(Wc, bc, out);
}

// round 17
// speedup vs baseline: 1.2372x; 1.2372x over previous
#include <cuda_runtime.h>
#include <cuda_bf16.h>
#include <stdint.h>
#include <math.h>

#define NHYP 4096
#define NPREM 4096
#define HEADS 4
#define ATN 128
#define DCTX 512
#define BERT 768
#define VD 192   // BERT/HEADS
#define QK_STRIDE 136   // bf16 elems per smem row (128 + 8 pad)
// scale * log2(e) folded into Q so score MMA yields log2-domain values
#define SC_LOG2E 0.127517425f

// ---------------- scratch (device globals; no allocations allowed) ----------------
__device__ __nv_bfloat16 g_Qhb[(size_t)HEADS * NHYP * ATN];    // [h][n][d]  (pre-scaled)
__device__ __nv_bfloat16 g_Khb[(size_t)HEADS * NPREM * ATN];   // [h][m][d]
__device__ __nv_bfloat16 g_Vt[(size_t)BERT * NPREM];           // [col][m] (col = h*192+e)
__device__ float g_att[(size_t)NHYP * BERT];
__device__ float g_h1[(size_t)NHYP * 256];
__device__ float g_h2[(size_t)NHYP * 128];
__device__ int   g_bp[NPREM];
__device__ int   g_bh[NHYP];
__device__ int   g_mlo[NHYP];
__device__ int   g_mhi[NHYP];
__device__ __nv_bfloat16 g_Wq_t[DCTX * DCTX];
__device__ __nv_bfloat16 g_Wk_t[DCTX * DCTX];
__device__ __nv_bfloat16 g_Wv_t[BERT * BERT];
__device__ __nv_bfloat16 g_W1_t[256 * (DCTX + BERT)];

// ================= warp-MMA / async helpers =================
__device__ __forceinline__ uint32_t smem_u32(const void* p) {
    uint32_t a;
    asm("{ .reg .u64 t; cvta.to.shared.u64 t, %1; cvt.u32.u64 %0, t; }" : "=r"(a) : "l"(p));
    return a;
}
__device__ __forceinline__ void ldm_x4(uint32_t* r, uint32_t addr) {
    asm volatile("ldmatrix.sync.aligned.m8n8.x4.shared.b16 {%0,%1,%2,%3}, [%4];"
        : "=r"(r[0]), "=r"(r[1]), "=r"(r[2]), "=r"(r[3]) : "r"(addr));
}
__device__ __forceinline__ void mma_bf16(float* c, const uint32_t* a, uint32_t b0, uint32_t b1) {
    asm volatile("mma.sync.aligned.m16n8k16.row.col.f32.bf16.bf16.f32 "
        "{%0,%1,%2,%3}, {%4,%5,%6,%7}, {%8,%9}, {%0,%1,%2,%3};"
        : "+f"(c[0]), "+f"(c[1]), "+f"(c[2]), "+f"(c[3])
        : "r"(a[0]), "r"(a[1]), "r"(a[2]), "r"(a[3]), "r"(b0), "r"(b1));
}
__device__ __forceinline__ void cp16(uint32_t dst, const void* src) {
    asm volatile("cp.async.cg.shared.global [%0], [%1], 16;" :: "r"(dst), "l"(src));
}
__device__ __forceinline__ float ex2f(float x) {
    float y;
    asm("ex2.approx.f32 %0, %1;" : "=f"(y) : "f"(x));
    return y;
}
__device__ __forceinline__ uint4 pack_bf16x8(float4 f0, float4 f1) {
    __nv_bfloat162 p0 = __floats2bfloat162_rn(f0.x, f0.y);
    __nv_bfloat162 p1 = __floats2bfloat162_rn(f0.z, f0.w);
    __nv_bfloat162 p2 = __floats2bfloat162_rn(f1.x, f1.y);
    __nv_bfloat162 p3 = __floats2bfloat162_rn(f1.z, f1.w);
    uint4 u;
    u.x = *(uint32_t*)&p0; u.y = *(uint32_t*)&p1;
    u.z = *(uint32_t*)&p2; u.w = *(uint32_t*)&p3;
    return u;
}

// ---------------- prep kernels ----------------
__device__ __forceinline__ void prep_batch_one(const int* __restrict__ raw, int* __restrict__ dst, int n)
{
    __shared__ int flag;
    int t = threadIdx.x;
    if (t == 0) flag = 0;
    __syncthreads();
    int acc = 0;
    for (int i = 2 * t + 1; i < n; i += 512) acc |= raw[i];
    if (acc) atomicOr(&flag, 1);
    __syncthreads();
    bool is32 = (flag != 0);
    for (int i = t; i < n; i += 256)
        dst[i] = is32 ? raw[i] : raw[2 * i];
}

__global__ void prep_batch2_kernel(const int* __restrict__ rawp, const int* __restrict__ rawh)
{
    if (blockIdx.x == 0) prep_batch_one(rawp, g_bp, NPREM);
    else                 prep_batch_one(rawh, g_bh, NHYP);
}

// masked premise columns for hyp row n form contiguous range [mlo, mhi) (batch_p sorted)
__global__ void prep_ranges_kernel()
{
    int n = blockIdx.x * 256 + threadIdx.x;
    int b = g_bh[n];
    int lo = 0, hi = NPREM;
    while (lo < hi) { int mid = (lo + hi) >> 1; if (g_bp[mid] < b) lo = mid + 1; else hi = mid; }
    int s = lo;
    lo = 0; hi = NPREM;
    while (lo < hi) { int mid = (lo + hi) >> 1; if (g_bp[mid] < b + 1) lo = mid + 1; else hi = mid; }
    g_mlo[n] = s;
    g_mhi[n] = lo;
}

// all 4 weight transposes (fp32 [R][C] -> bf16 [C][R]) in one launch; 1408 tiles
__global__ void transpose_all_kernel(const float* __restrict__ Wq, const float* __restrict__ Wk,
                                     const float* __restrict__ Wv, const float* __restrict__ W1)
{
    __shared__ float tile[32][33];
    int t = blockIdx.x;
    const float* W;
    __nv_bfloat16* Wt;
    int R, C;
    if (t < 256)       { W = Wq; Wt = g_Wq_t; R = DCTX; C = DCTX; }
    else if (t < 512)  { t -= 256;  W = Wk; Wt = g_Wk_t; R = DCTX; C = DCTX; }
    else if (t < 1088) { t -= 512;  W = Wv; Wt = g_Wv_t; R = BERT; C = BERT; }
    else               { t -= 1088; W = W1; Wt = g_W1_t; R = DCTX + BERT; C = 256; }
    int tilesX = C >> 5;
    int c0 = (t % tilesX) * 32, r0 = (t / tilesX) * 32;
    int tx = threadIdx.x, ty = threadIdx.y;   // 32 x 8
#pragma unroll
    for (int j = 0; j < 4; j++)
        tile[ty + j * 8][tx] = W[(size_t)(r0 + ty + j * 8) * C + (c0 + tx)];
    __syncthreads();
#pragma unroll
    for (int j = 0; j < 4; j++)
        Wt[(size_t)(c0 + ty + j * 8) * R + (r0 + tx)] = __float2bfloat16(tile[tx][ty + j * 8]);
}

// ---------------- merged bf16 warp-MMA projections (V first for LPT scheduling) ----------------
// block decode: [0,192) V (long jobs), [192,320) Q, [320,448) K
__global__ __launch_bounds__(256, 2) void proj_all(const float* __restrict__ ctx_h,
                                                   const float* __restrict__ ctx_p,
                                                   const float* __restrict__ lhs_p,
                                                   const float* __restrict__ bq,
                                                   const float* __restrict__ bk,
                                                   const float* __restrict__ bv)
{
    extern __shared__ __nv_bfloat16 smem[];
    __nv_bfloat16* As = smem;
    int tid = threadIdx.x, wid = tid >> 5, lane = tid & 31;

    int t = blockIdx.x;
    int mode, K, c0, n0;
    const float* A;
    const __nv_bfloat16* Wt;
    const float* bias;
    if (t < 192)      { mode = 2; K = BERT; A = lhs_p; Wt = g_Wv_t; bias = bv; c0 = (t % 6) * 128; n0 = (t / 6) * 128; }
    else if (t < 320) { t -= 192; mode = 0; K = DCTX; A = ctx_h; Wt = g_Wq_t; bias = bq; c0 = (t & 3) * 128; n0 = (t >> 2) * 128; }
    else              { t -= 320; mode = 1; K = DCTX; A = ctx_p; Wt = g_Wk_t; bias = bk; c0 = (t & 3) * 128; n0 = (t >> 2) * 128; }

    uint32_t bsu = smem_u32(smem) + 128 * QK_STRIDE * 2;

    int wr = wid >> 1, wc = wid & 1;
    uint32_t abase = smem_u32(As) + (uint32_t)(wr * 32 + (lane & 15)) * (QK_STRIDE * 2) + (lane >> 4) * 16;
    uint32_t bbase = bsu + (uint32_t)(wc * 64 + (lane & 7) + ((lane & 16) >> 1)) * (QK_STRIDE * 2)
                     + ((lane >> 3) & 1) * 16;

    float c[2][8][4] = {};
    for (int kt = 0; kt < K / 128; kt++) {
        int k0 = kt * 128;
        for (int i = tid; i < 2048; i += 256) {
            int r = i >> 4, cc = (i & 15) * 8;
            cp16(bsu + (uint32_t)(r * QK_STRIDE + cc) * 2, &Wt[(size_t)(c0 + r) * K + k0 + cc]);
        }
        asm volatile("cp.async.commit_group;" ::: "memory");
        for (int i = tid; i < 2048; i += 256) {
            int r = i >> 4, cc = (i & 15) * 8;
            const float* ap = &A[(size_t)(n0 + r) * K + k0 + cc];
            *(uint4*)&As[r * QK_STRIDE + cc] = pack_bf16x8(*(const float4*)ap, *(const float4*)(ap + 4));
        }
        asm volatile("cp.async.wait_group 0;" ::: "memory");
        __syncthreads();
#pragma unroll
        for (int s = 0; s < 8; s++) {
            uint32_t a[2][4], b[4][4];
#pragma unroll
            for (int mi = 0; mi < 2; mi++) ldm_x4(a[mi], abase + mi * 16 * QK_STRIDE * 2 + s * 32);
#pragma unroll
            for (int ni = 0; ni < 4; ni++) ldm_x4(b[ni], bbase + ni * 16 * QK_STRIDE * 2 + s * 32);
#pragma unroll
            for (int mi = 0; mi < 2; mi++)
#pragma unroll
                for (int nb = 0; nb < 8; nb++)
                    mma_bf16(c[mi][nb], a[mi], b[nb >> 1][(nb & 1) * 2], b[nb >> 1][(nb & 1) * 2 + 1]);
        }
        __syncthreads();
    }

    int g = lane >> 2, tq = lane & 3;
#pragma unroll
    for (int mi = 0; mi < 2; mi++) {
        int row = n0 + wr * 32 + mi * 16 + g;
#pragma unroll
        for (int nb = 0; nb < 8; nb++) {
            int col = c0 + wc * 64 + nb * 8 + tq * 2;
            float b0 = bias[col], b1 = bias[col + 1];
            float v0 = c[mi][nb][0] + b0, v1 = c[mi][nb][1] + b1;
            float v2 = c[mi][nb][2] + b0, v3 = c[mi][nb][3] + b1;
            if (mode == 0) {
                v0 *= SC_LOG2E; v1 *= SC_LOG2E; v2 *= SC_LOG2E; v3 *= SC_LOG2E;
                g_Qhb[((size_t)(col & 3) * NHYP + row) * ATN + (col >> 2)]             = __float2bfloat16(v0);
                g_Qhb[((size_t)((col + 1) & 3) * NHYP + row) * ATN + ((col + 1) >> 2)] = __float2bfloat16(v1);
                g_Qhb[((size_t)(col & 3) * NHYP + row + 8) * ATN + (col >> 2)]             = __float2bfloat16(v2);
                g_Qhb[((size_t)((col + 1) & 3) * NHYP + row + 8) * ATN + ((col + 1) >> 2)] = __float2bfloat16(v3);
            } else if (mode == 1) {
                g_Khb[((size_t)(col & 3) * NPREM + row) * ATN + (col >> 2)]             = __float2bfloat16(v0);
                g_Khb[((size_t)((col + 1) & 3) * NPREM + row) * ATN + ((col + 1) >> 2)] = __float2bfloat16(v1);
                g_Khb[((size_t)(col & 3) * NPREM + row + 8) * ATN + (col >> 2)]             = __float2bfloat16(v2);
                g_Khb[((size_t)((col + 1) & 3) * NPREM + row + 8) * ATN + ((col + 1) >> 2)] = __float2bfloat16(v3);
            } else {
                g_Vt[(size_t)col * NPREM + row]           = __float2bfloat16(v0);
                g_Vt[(size_t)(col + 1) * NPREM + row]     = __float2bfloat16(v1);
                g_Vt[(size_t)col * NPREM + row + 8]       = __float2bfloat16(v2);
                g_Vt[(size_t)(col + 1) * NPREM + row + 8] = __float2bfloat16(v3);
            }
        }
    }
}

// ---------------- bf16 warp-MMA MLP1 (64-row tile -> 128 CTAs, 2 CTAs/SM) ----------------
__global__ __launch_bounds__(256, 2) void mlp1_bf(const float* __restrict__ ctx_h,
                                                  const float* __restrict__ lhs_h,
                                                  const __nv_bfloat16* __restrict__ Wt,
                                                  const float* __restrict__ bias)
{
    const int K = DCTX + BERT;
    extern __shared__ __nv_bfloat16 smem[];
    __nv_bfloat16* As = smem;
    uint32_t bsu = smem_u32(smem) + 64 * QK_STRIDE * 2;
    int tid = threadIdx.x, wid = tid >> 5, lane = tid & 31;
    int c0 = blockIdx.x * 128, n0 = blockIdx.y * 64;

    int wr = wid >> 1, wc = wid & 1;
    uint32_t abase = smem_u32(As) + (uint32_t)(wr * 16 + (lane & 15)) * (QK_STRIDE * 2) + (lane >> 4) * 16;
    uint32_t bbase = bsu + (uint32_t)(wc * 64 + (lane & 7) + ((lane & 16) >> 1)) * (QK_STRIDE * 2)
                     + ((lane >> 3) & 1) * 16;

    float c[8][4] = {};
    for (int kt = 0; kt < K / 128; kt++) {
        int k0 = kt * 128;
        for (int i = tid; i < 2048; i += 256) {
            int r = i >> 4, cc = (i & 15) * 8;
            cp16(bsu + (uint32_t)(r * QK_STRIDE + cc) * 2, &Wt[(size_t)(c0 + r) * K + k0 + cc]);
        }
        asm volatile("cp.async.commit_group;" ::: "memory");
        for (int i = tid; i < 1024; i += 256) {
            int r = i >> 4, cc = (i & 15) * 8;
            int kg = k0 + cc;
            int row = n0 + r;
            float4 f0, f1;
            if (kg < DCTX) {
                const float* ap = &ctx_h[(size_t)row * DCTX + kg];
                f0 = *(const float4*)ap; f1 = *(const float4*)(ap + 4);
            } else {
                int idx = kg - DCTX;
                const float* lp = &lhs_h[(size_t)row * BERT + idx];
                const float* tp = &g_att[(size_t)row * BERT + idx];
                float4 l0 = *(const float4*)lp, l1 = *(const float4*)(lp + 4);
                float4 a0 = *(const float4*)tp, a1 = *(const float4*)(tp + 4);
                f0 = make_float4(l0.x - a0.x, l0.y - a0.y, l0.z - a0.z, l0.w - a0.w);
                f1 = make_float4(l1.x - a1.x, l1.y - a1.y, l1.z - a1.z, l1.w - a1.w);
            }
            *(uint4*)&As[r * QK_STRIDE + cc] = pack_bf16x8(f0, f1);
        }
        asm volatile("cp.async.wait_group 0;" ::: "memory");
        __syncthreads();
#pragma unroll
        for (int s = 0; s < 8; s++) {
            uint32_t a[4], b[4][4];
            ldm_x4(a, abase + s * 32);
#pragma unroll
            for (int ni = 0; ni < 4; ni++) ldm_x4(b[ni], bbase + ni * 16 * QK_STRIDE * 2 + s * 32);
#pragma unroll
            for (int nb = 0; nb < 8; nb++)
                mma_bf16(c[nb], a, b[nb >> 1][(nb & 1) * 2], b[nb >> 1][(nb & 1) * 2 + 1]);
        }
        __syncthreads();
    }

    int g = lane >> 2, tq = lane & 3;
    int row = n0 + wr * 16 + g;
#pragma unroll
    for (int nb = 0; nb < 8; nb++) {
        int col = c0 + wc * 64 + nb * 8 + tq * 2;
        float vv[4] = { c[nb][0] + bias[col], c[nb][1] + bias[col + 1],
                        c[nb][2] + bias[col], c[nb][3] + bias[col + 1] };
#pragma unroll
        for (int q = 0; q < 4; q++)
            vv[q] = 0.5f * vv[q] * (1.0f + erff(vv[q] * 0.70710678118654752f));
        g_h1[(size_t)row * 256 + col]           = vv[0];
        g_h1[(size_t)row * 256 + col + 1]       = vv[1];
        g_h1[(size_t)(row + 8) * 256 + col]     = vv[2];
        g_h1[(size_t)(row + 8) * 256 + col + 1] = vv[3];
    }
}

// ---------------- fused flash attention (256 thr; fixed-max log2 softmax, range masking) ----------------
// Tile processed in two m-halves to cap register pressure; Q fragments hoisted (tile-invariant).
#define FL_KOFF   (128 * QK_STRIDE)
#define FL_VOFF   (384 * QK_STRIDE)
#define FL_SMEM   (768 * QK_STRIDE * 2)
#define FL_NT     (NPREM / 128)
__global__ __launch_bounds__(256) void attn_flash()
{
    extern __shared__ __nv_bfloat16 smem[];
    __nv_bfloat16* Qs = smem;
    int tid = threadIdx.x, wid = tid >> 5, lane = tid & 31;
    int n0 = blockIdx.x * 128, h = blockIdx.y;
    int e0g = h * VD;
    const __nv_bfloat16* Q  = g_Qhb + (size_t)h * NHYP * ATN;
    const __nv_bfloat16* Kp = g_Khb + (size_t)h * NPREM * ATN;

    uint32_t ksu = smem_u32(smem) + FL_KOFF * 2;
    uint32_t vsu = smem_u32(smem) + FL_VOFF * 2;

    for (int i = tid; i < 2048; i += 256) {
        int r = i >> 4, c = (i & 15) * 8;
        *(uint4*)&Qs[r * QK_STRIDE + c] = *(const uint4*)&Q[(size_t)(n0 + r) * ATN + c];
    }

    auto issue = [&](int tt) {
        int b = tt & 1;
        int m0 = tt * 128;
        uint32_t kd = ksu + (uint32_t)b * (128 * QK_STRIDE * 2);
        uint32_t vd = vsu + (uint32_t)b * (192 * QK_STRIDE * 2);
        for (int i = tid; i < 2048; i += 256) {
            int r = i >> 4, c = (i & 15) * 8;
            cp16(kd + (uint32_t)(r * QK_STRIDE + c) * 2, Kp + (size_t)(m0 + r) * ATN + c);
        }
        for (int i = tid; i < 3072; i += 256) {
            int r = i >> 4, c = (i & 15) * 8;
            cp16(vd + (uint32_t)(r * QK_STRIDE + c) * 2, g_Vt + (size_t)(e0g + r) * NPREM + m0 + c);
        }
        asm volatile("cp.async.commit_group;" ::: "memory");
    };

    issue(0);

    int g = lane >> 2, tq = lane & 3;
    int r0g = n0 + wid * 16 + g;
    unsigned mlo0 = (unsigned)g_mlo[r0g];
    unsigned mw0  = (unsigned)(g_mhi[r0g] - g_mlo[r0g]);
    unsigned mlo1 = (unsigned)g_mlo[r0g + 8];
    unsigned mw1  = (unsigned)(g_mhi[r0g + 8] - g_mlo[r0g + 8]);

    uint32_t qbase = smem_u32(Qs) + (uint32_t)(wid * 16 + (lane & 15)) * (QK_STRIDE * 2) + (lane >> 4) * 16;
    uint32_t kvlane = (uint32_t)((lane & 7) + ((lane & 16) >> 1)) * (QK_STRIDE * 2) + ((lane >> 3) & 1) * 16;

    // barrier so Q smem is fully written before fragment preload
    __syncthreads();
    uint32_t qfrag[8][4];
#pragma unroll
    for (int ks = 0; ks < 8; ks++) ldm_x4(qfrag[ks], qbase + ks * 32);

    float l0 = 0.f, l1 = 0.f;
    float pacc[24][4] = {};

    for (int t = 0; t < FL_NT; t++) {
        int b = t & 1;
        if (t + 1 < FL_NT) {
            issue(t + 1);
            asm volatile("cp.async.wait_group 1;" ::: "memory");
        } else {
            asm volatile("cp.async.wait_group 0;" ::: "memory");
        }
        __syncthreads();

        uint32_t kb0 = ksu + (uint32_t)b * (128 * QK_STRIDE * 2) + kvlane;
        uint32_t vbase = vsu + (uint32_t)b * (192 * QK_STRIDE * 2) + kvlane;
        int m0 = t * 128;

#pragma unroll
        for (int half = 0; half < 2; half++) {
            uint32_t kb = kb0 + (uint32_t)half * 64 * (QK_STRIDE * 2);

            float sacc[8][4] = {};
#pragma unroll
            for (int ks = 0; ks < 8; ks++) {
#pragma unroll
                for (int nj = 0; nj < 4; nj++) {
                    uint32_t bb[4];
                    ldm_x4(bb, kb + nj * 16 * (QK_STRIDE * 2) + ks * 32);
                    mma_bf16(sacc[2 * nj],     qfrag[ks], bb[0], bb[1]);
                    mma_bf16(sacc[2 * nj + 1], qfrag[ks], bb[2], bb[3]);
                }
            }

            uint32_t pfrag[4][4];
#pragma unroll
            for (int j = 0; j < 8; j++) {
                unsigned ci = (unsigned)(m0 + half * 64 + j * 8 + tq * 2);
                float v0 = ex2f(sacc[j][0]);
                float v1 = ex2f(sacc[j][1]);
                float v2 = ex2f(sacc[j][2]);
                float v3 = ex2f(sacc[j][3]);
                if (ci - mlo0 < mw0)     v0 = 0.f;
                if (ci + 1 - mlo0 < mw0) v1 = 0.f;
                if (ci - mlo1 < mw1)     v2 = 0.f;
                if (ci + 1 - mlo1 < mw1) v3 = 0.f;
                l0 += v0 + v1;
                l1 += v2 + v3;
                __nv_bfloat162 p01 = __floats2bfloat162_rn(v0, v1);
                __nv_bfloat162 p23 = __floats2bfloat162_rn(v2, v3);
                pfrag[j >> 1][(j & 1) * 2]     = *(uint32_t*)&p01;
                pfrag[j >> 1][(j & 1) * 2 + 1] = *(uint32_t*)&p23;
            }

#pragma unroll
            for (int ks = 0; ks < 4; ks++) {
                int ksg = half * 4 + ks;
#pragma unroll
                for (int ej = 0; ej < 12; ej++) {
                    uint32_t bb[4];
                    ldm_x4(bb, vbase + ej * 16 * (QK_STRIDE * 2) + ksg * 32);
                    mma_bf16(pacc[2 * ej],     pfrag[ks], bb[0], bb[1]);
                    mma_bf16(pacc[2 * ej + 1], pfrag[ks], bb[2], bb[3]);
                }
            }
        }
        __syncthreads();
    }

    l0 += __shfl_xor_sync(0xffffffffu, l0, 1);
    l0 += __shfl_xor_sync(0xffffffffu, l0, 2);
    l1 += __shfl_xor_sync(0xffffffffu, l1, 1);
    l1 += __shfl_xor_sync(0xffffffffu, l1, 2);

    float inv0 = 1.0f / l0, inv1 = 1.0f / l1;
#pragma unroll
    for (int ej = 0; ej < 24; ej++) {
        int eg = e0g + ej * 8 + tq * 2;
        *(float2*)&g_att[(size_t)r0g * BERT + eg]       = make_float2(pacc[ej][0] * inv0, pacc[ej][1] * inv0);
        *(float2*)&g_att[(size_t)(r0g + 8) * BERT + eg] = make_float2(pacc[ej][2] * inv1, pacc[ej][3] * inv1);
    }
}

// ---------------- h2 = LayerNorm(h1 @ W2), 32-row tiles (grid 128) ----------------
__global__ void mlp2_kernel(const float* __restrict__ W2, const float* __restrict__ lng,
                            const float* __restrict__ lnb)
{
    __shared__ float smbuf[32 * 36 + 32 * 132 + 64];
    float* Fts = smbuf;
    float* Ws2 = smbuf + 32 * 36;
    int tid = threadIdx.x;
    int n0 = blockIdx.x * 32;
    int tx = tid & 15, ty = tid >> 4;
    float acc[2][8] = {};
    for (int k0 = 0; k0 < 256; k0 += 32) {
#pragma unroll
        for (int it = 0; it < 4; it++) {
            int e = tid + it * 256;
            int r = e >> 5, kk = e & 31;
            Fts[kk * 36 + r] = g_h1[(size_t)(n0 + r) * 256 + (k0 + kk)];
        }
#pragma unroll
        for (int it = 0; it < 16; it++) {
            int e = tid + it * 256;
            int kk = e >> 7, c = e & 127;
            Ws2[kk * 132 + c] = W2[(size_t)(k0 + kk) * 128 + c];
        }
        __syncthreads();
#pragma unroll
        for (int kk = 0; kk < 32; kk++) {
            float2 a  = *(const float2*)&Fts[kk * 36 + ty * 2];
            float4 b0 = *(const float4*)&Ws2[kk * 132 + tx * 4];
            float4 b1v = *(const float4*)&Ws2[kk * 132 + 64 + tx * 4];
            float av[2] = {a.x, a.y};
            float bv[8] = {b0.x, b0.y, b0.z, b0.w, b1v.x, b1v.y, b1v.z, b1v.w};
#pragma unroll
            for (int i = 0; i < 2; i++)
#pragma unroll
                for (int j = 0; j < 8; j++)
                    acc[i][j] += av[i] * bv[j];
        }
        __syncthreads();
    }
    float* H2s = smbuf;
    float* mu  = smbuf + 32 * 132;
    float* rs  = mu + 32;
#pragma unroll
    for (int i = 0; i < 2; i++) {
        int r = ty * 2 + i;
#pragma unroll
        for (int j = 0; j < 8; j++) {
            int c = (j < 4) ? (tx * 4 + j) : (64 + tx * 4 + (j - 4));
            H2s[r * 132 + c] = acc[i][j];
        }
    }
    __syncthreads();
    if (tid < 32) {
        float s = 0.f;
        for (int c = 0; c < 128; c++) s += H2s[tid * 132 + c];
        float m = s * (1.0f / 128.0f);
        float vv = 0.f;
        for (int c = 0; c < 128; c++) { float d = H2s[tid * 132 + c] - m; vv += d * d; }
        mu[tid] = m;
        rs[tid] = rsqrtf(vv * (1.0f / 128.0f) + 1e-5f);
    }
    __syncthreads();
#pragma unroll
    for (int it = 0; it < 16; it++) {
        int e = tid + it * 256;
        int r = e >> 7, c = e & 127;
        float v = (H2s[r * 132 + c] - mu[r]) * rs[r] * lng[c] + lnb[c];
        g_h2[(size_t)(n0 + r) * 128 + c] = v;
    }
}

// ---------------- segment-mean pool + classifier ----------------
__global__ void final_kernel(const float* __restrict__ Wc,
                             const float* __restrict__ bc, float* __restrict__ out)
{
    int b = blockIdx.x;
    int c = threadIdx.x;
    int lo = 0, hi = NHYP;
    while (lo < hi) { int mid = (lo + hi) >> 1; if (g_bh[mid] < b) lo = mid + 1; else hi = mid; }
    int start = lo;
    lo = 0; hi = NHYP;
    while (lo < hi) { int mid = (lo + hi) >> 1; if (g_bh[mid] < b + 1) lo = mid + 1; else hi = mid; }
    int end = lo;
    float s = 0.f;
    for (int r = start; r < end; r++) s += g_h2[(size_t)r * 128 + c];
    int cnt = end - start;
    float pooled = s / (float)(cnt > 1 ? cnt : 1);
    __shared__ float ps[128];
    ps[c] = pooled;
    __syncthreads();
    if (c < 3) {
        float o = bc[c];
        for (int j = 0; j < 128; j++) o += ps[j] * Wc[j * 3 + c];
        out[b * 3 + c] = o;
    }
}

// ---------------- launcher ----------------
#define PROJ_SMEM  (2 * 128 * QK_STRIDE * 2)
#define MLP1_SMEM  ((64 + 128) * QK_STRIDE * 2)

extern "C" void kernel_launch(void* const* d_in, const int* in_sizes, int n_in,
                              void* d_out, int out_size)
{
    const float* ctx_p = (const float*)d_in[0];
    const float* ctx_h = (const float*)d_in[1];
    const float* lhs_p = (const float*)d_in[2];
    const float* lhs_h = (const float*)d_in[3];
    const int* batch_p_raw = (const int*)d_in[4];
    const int* batch_h_raw = (const int*)d_in[5];
    const float* Wq = (const float*)d_in[6];
    const float* bq = (const float*)d_in[7];
    const float* Wk = (const float*)d_in[8];
    const float* bk = (const float*)d_in[9];
    const float* Wv = (const float*)d_in[10];
    const float* bv = (const float*)d_in[11];
    const float* W1 = (const float*)d_in[12];
    const float* b1 = (const float*)d_in[13];
    const float* W2 = (const float*)d_in[14];
    const float* lng = (const float*)d_in[15];
    const float* lnb = (const float*)d_in[16];
    const float* Wc = (const float*)d_in[17];
    const float* bc = (const float*)d_in[18];
    float* out = (float*)d_out;

    __nv_bfloat16* w1_t; cudaGetSymbolAddress((void**)&w1_t, g_W1_t);

    cudaFuncSetAttribute(proj_all,   cudaFuncAttributeMaxDynamicSharedMemorySize, PROJ_SMEM);
    cudaFuncSetAttribute(mlp1_bf,    cudaFuncAttributeMaxDynamicSharedMemorySize, MLP1_SMEM);
    cudaFuncSetAttribute(attn_flash, cudaFuncAttributeMaxDynamicSharedMemorySize, FL_SMEM);

    prep_batch2_kernel<<<2, 256>>>(batch_p_raw, batch_h_raw);
    prep_ranges_kernel<<<NHYP / 256, 256>>>();

    transpose_all_kernel<<<1408, dim3(32, 8)>>>(Wq, Wk, Wv, W1);

    proj_all<<<448, 256, PROJ_SMEM>>>(ctx_h, ctx_p, lhs_p, bq, bk, bv);

    attn_flash<<<dim3(NHYP / 128, HEADS), 256, FL_SMEM>>>();

    mlp1_bf<<<dim3(2, NHYP / 64), 256, MLP1_SMEM>>>(ctx_h, lhs_h, w1_t, b1);
    mlp2_kernel<<<NHYP / 32, 256>>>(W2, lng, lnb);
    final_kernel<<<32, 128>>>(Wc, bc, out);
}